// round 1
// baseline (speedup 1.0000x reference)
#include <cuda_runtime.h>
#include <cstdint>

// Problem constants (fixed by the dataset)
#define NUM_AUTHOR 16604
#define NUM_NODES  29059
#define DIM        300
#define NB         32768          // batch of query nodes
#define NE         1048576        // edges
#define KP         928            // padded K (3*300=900 -> 928 = 29*32)
#define NP         304            // padded N for W (300 -> 304)

// Scratch (device globals: allocation-free rule)
__device__ float g_combined[(size_t)NB * KP];   // [B, 928] tf32-rounded, cols 900..927 = 0
__device__ float g_wpad[NP * KP];               // [304, 928] tf32-rounded W1, padded with 0
__device__ int   g_off[NB + 1];                 // segment start offsets

__device__ __forceinline__ float tf32r(float x) {
    uint32_t u;
    asm("cvt.rna.tf32.f32 %0, %1;" : "=r"(u) : "f"(x));
    return __uint_as_float(u);
}

// ---------------------------------------------------------------------------
// Kernel 1: segment offsets via binary search (seg is sorted)
// ---------------------------------------------------------------------------
__global__ void offsets_kernel(const int* __restrict__ seg) {
    int i = blockIdx.x * blockDim.x + threadIdx.x;
    if (i > NB) return;
    int lo = 0, hi = NE;
    while (lo < hi) {
        int mid = (lo + hi) >> 1;
        if (seg[mid] < i) lo = mid + 1; else hi = mid;
    }
    g_off[i] = lo;
}

// ---------------------------------------------------------------------------
// Kernel 2: pad + tf32-round W1 into g_wpad [304 x 928]
// ---------------------------------------------------------------------------
__global__ void padw_kernel(const float* __restrict__ W1) {
    int idx = blockIdx.x * blockDim.x + threadIdx.x;
    if (idx >= NP * KP) return;
    int o = idx / KP, k = idx % KP;
    float v = 0.0f;
    if (o < DIM && k < 3 * DIM) v = W1[o * (3 * DIM) + k];
    g_wpad[idx] = tf32r(v);
}

// ---------------------------------------------------------------------------
// Kernel 3: segment aggregation -> combined = [self | t1 | t2 | 0-pad]
// one block per query node; thread = one embedding dim
// ---------------------------------------------------------------------------
__global__ void __launch_bounds__(320) agg_kernel(
    const int* __restrict__ nodes,
    const int* __restrict__ neighbors,
    const float* __restrict__ emb)
{
    int b   = blockIdx.x;
    int tid = threadIdx.x;
    int start = g_off[b];
    int end   = g_off[b + 1];
    int node  = nodes[b];
    bool selfA = node < NUM_AUTHOR;
    float* cb = g_combined + (size_t)b * KP;

    if (tid < DIM) {
        float selfv = emb[node * DIM + tid];
        float acc1 = 0.f, acc2 = 0.f;
        int c1 = 0;
        int e = start;
        for (; e + 4 <= end; e += 4) {
            int n0 = neighbors[e];
            int n1 = neighbors[e + 1];
            int n2 = neighbors[e + 2];
            int n3 = neighbors[e + 3];
            float v0 = emb[n0 * DIM + tid];
            float v1 = emb[n1 * DIM + tid];
            float v2 = emb[n2 * DIM + tid];
            float v3 = emb[n3 * DIM + tid];
            bool s0 = (n0 < NUM_AUTHOR) == selfA;
            bool s1 = (n1 < NUM_AUTHOR) == selfA;
            bool s2 = (n2 < NUM_AUTHOR) == selfA;
            bool s3 = (n3 < NUM_AUTHOR) == selfA;
            acc1 += s0 ? v0 : 0.f;  acc2 += s0 ? 0.f : v0;  c1 += s0;
            acc1 += s1 ? v1 : 0.f;  acc2 += s1 ? 0.f : v1;  c1 += s1;
            acc1 += s2 ? v2 : 0.f;  acc2 += s2 ? 0.f : v2;  c1 += s2;
            acc1 += s3 ? v3 : 0.f;  acc2 += s3 ? 0.f : v3;  c1 += s3;
        }
        for (; e < end; e++) {
            int n = neighbors[e];
            float v = emb[n * DIM + tid];
            bool s = (n < NUM_AUTHOR) == selfA;
            acc1 += s ? v : 0.f;  acc2 += s ? 0.f : v;  c1 += s;
        }
        int tot = end - start;
        int c2 = tot - c1;
        float t1 = (c1 > 0) ? acc1 / (float)c1 : 1.0f;
        float t2 = (c2 > 0) ? acc2 / (float)c2 : 1.0f;
        __stcs(&cb[tid],            tf32r(selfv));
        __stcs(&cb[DIM + tid],      tf32r(t1));
        __stcs(&cb[2 * DIM + tid],  tf32r(t2));
    }
    if (tid < KP - 3 * DIM) {   // zero-pad cols 900..927
        __stcs(&cb[3 * DIM + tid], 0.0f);
    }
}

// ---------------------------------------------------------------------------
// Kernel 4: GEMM  out[32768,300] = combined[32768,928] @ Wpad^T + b1
// tf32 mma.sync m16n8k8 ; BM=128, BN=64, BK=32 ; 8 warps (4M x 2N)
// grid = (5 N-tiles [x fast -> A shared in L2], 256 M-tiles)
// ---------------------------------------------------------------------------
#define BM 128
#define BN 64
#define BK 32
#define SSTR (BK + 4)   // smem row stride 36: banks = (4*gid + tig) -> conflict-free

__global__ void __launch_bounds__(256) gemm_kernel(
    const float* __restrict__ b1,
    float* __restrict__ out)
{
    __shared__ float As[BM][SSTR];
    __shared__ float Bs[BN][SSTR];

    int bn = blockIdx.x;      // 0..4
    int bm = blockIdx.y;      // 0..255
    int tid  = threadIdx.x;
    int warp = tid >> 5, lane = tid & 31;
    int wm = warp & 3, wn = warp >> 2;
    int gid = lane >> 2, tig = lane & 3;

    const float* Ag = g_combined + (size_t)(bm * BM) * KP;
    const float* Bg = g_wpad + (size_t)(bn * BN) * KP;

    float c[2][4][4];
#pragma unroll
    for (int mt = 0; mt < 2; mt++)
#pragma unroll
        for (int nt = 0; nt < 4; nt++)
#pragma unroll
            for (int i = 0; i < 4; i++) c[mt][nt][i] = 0.f;

    for (int kt = 0; kt < KP / BK; kt++) {
        // load A tile: 128x32 = 1024 float4, 4 per thread
#pragma unroll
        for (int i = 0; i < 4; i++) {
            int lin = tid + i * 256;
            int row = lin >> 3, c4 = lin & 7;
            float4 v = *(const float4*)(Ag + (size_t)row * KP + kt * BK + c4 * 4);
            *(float4*)(&As[row][c4 * 4]) = v;
        }
        // load B tile: 64x32 = 512 float4, 2 per thread
#pragma unroll
        for (int i = 0; i < 2; i++) {
            int lin = tid + i * 256;
            int row = lin >> 3, c4 = lin & 7;
            float4 v = *(const float4*)(Bg + (size_t)row * KP + kt * BK + c4 * 4);
            *(float4*)(&Bs[row][c4 * 4]) = v;
        }
        __syncthreads();

#pragma unroll
        for (int ks = 0; ks < 4; ks++) {
            int k0 = ks * 8;
            uint32_t a[2][4], bfr[4][2];
#pragma unroll
            for (int mt = 0; mt < 2; mt++) {
                int r = wm * 32 + mt * 16 + gid;
                a[mt][0] = __float_as_uint(As[r][k0 + tig]);
                a[mt][1] = __float_as_uint(As[r + 8][k0 + tig]);
                a[mt][2] = __float_as_uint(As[r][k0 + tig + 4]);
                a[mt][3] = __float_as_uint(As[r + 8][k0 + tig + 4]);
            }
#pragma unroll
            for (int nt = 0; nt < 4; nt++) {
                int n = wn * 32 + nt * 8 + gid;
                bfr[nt][0] = __float_as_uint(Bs[n][k0 + tig]);
                bfr[nt][1] = __float_as_uint(Bs[n][k0 + tig + 4]);
            }
#pragma unroll
            for (int mt = 0; mt < 2; mt++)
#pragma unroll
                for (int nt = 0; nt < 4; nt++) {
                    asm volatile(
                        "mma.sync.aligned.m16n8k8.row.col.f32.tf32.tf32.f32 "
                        "{%0,%1,%2,%3},{%4,%5,%6,%7},{%8,%9},{%0,%1,%2,%3};"
                        : "+f"(c[mt][nt][0]), "+f"(c[mt][nt][1]),
                          "+f"(c[mt][nt][2]), "+f"(c[mt][nt][3])
                        : "r"(a[mt][0]), "r"(a[mt][1]), "r"(a[mt][2]), "r"(a[mt][3]),
                          "r"(bfr[nt][0]), "r"(bfr[nt][1]));
                }
        }
        __syncthreads();
    }

    // epilogue: +b1, store (guard N=300)
#pragma unroll
    for (int mt = 0; mt < 2; mt++) {
#pragma unroll
        for (int nt = 0; nt < 4; nt++) {
            int gn = bn * BN + wn * 32 + nt * 8 + tig * 2;
            if (gn < DIM) {
                float bb0 = b1[gn], bb1 = b1[gn + 1];
                int gm0 = bm * BM + wm * 32 + mt * 16 + gid;
                float2 v0, v1;
                v0.x = c[mt][nt][0] + bb0;  v0.y = c[mt][nt][1] + bb1;
                v1.x = c[mt][nt][2] + bb0;  v1.y = c[mt][nt][3] + bb1;
                *(float2*)(out + (size_t)gm0 * DIM + gn) = v0;
                *(float2*)(out + (size_t)(gm0 + 8) * DIM + gn) = v1;
            }
        }
    }
}

// ---------------------------------------------------------------------------
extern "C" void kernel_launch(void* const* d_in, const int* in_sizes, int n_in,
                              void* d_out, int out_size) {
    const int*   nodes     = (const int*)d_in[0];
    const int*   seg       = (const int*)d_in[1];
    const int*   neighbors = (const int*)d_in[2];
    const float* emb       = (const float*)d_in[3];
    const float* W1        = (const float*)d_in[4];
    const float* b1        = (const float*)d_in[5];
    float*       out       = (float*)d_out;

    offsets_kernel<<<(NB + 1 + 255) / 256, 256>>>(seg);
    padw_kernel<<<(NP * KP + 255) / 256, 256>>>(W1);
    agg_kernel<<<NB, 320>>>(nodes, neighbors, emb);
    dim3 grid(5, NB / BM);   // x = N-tile (fast) so N-tiles of one M-tile share A in L2
    gemm_kernel<<<grid, 256>>>(b1, out);
}